// round 8
// baseline (speedup 1.0000x reference)
#include <cuda_runtime.h>
#include <cuda_fp16.h>
#include <cstdint>
#include <math.h>

#define NB 16
#define NA 2048
#define ND 512
#define NR 10
#define INV_SQRT_DK 0.04419417382415922f  // 1/sqrt(512)

// Scratch (no device allocations allowed)
__device__ float  g_left[(size_t)NB * NA * NR];    // left proj, pre-scaled by 1/sqrt(dk)
__device__ float  g_rightT[(size_t)NB * NA * NR];  // right proj, [b][c][r]
__device__ __half g_xh[(size_t)NB * NA * ND];      // x pre-converted to half

__device__ __forceinline__ uint32_t smem_u32(const void* p) {
    uint32_t a;
    asm("{ .reg .u64 t; cvta.to.shared.u64 t, %1; cvt.u32.u64 %0, t; }" : "=r"(a) : "l"(p));
    return a;
}
__device__ __forceinline__ void cp_async16(uint32_t saddr, const void* gptr) {
    asm volatile("cp.async.cg.shared.global [%0], [%1], 16;" :: "r"(saddr), "l"(gptr) : "memory");
}
#define CP_COMMIT() asm volatile("cp.async.commit_group;" ::: "memory")
#define CP_WAIT0()  asm volatile("cp.async.wait_group 0;" ::: "memory")

__device__ __forceinline__ void mma_f16(float* d, const uint32_t* a, const uint32_t* bfr) {
    asm volatile(
        "mma.sync.aligned.m16n8k16.row.col.f32.f16.f16.f32 "
        "{%0,%1,%2,%3}, {%4,%5,%6,%7}, {%8,%9}, {%0,%1,%2,%3};"
        : "+f"(d[0]), "+f"(d[1]), "+f"(d[2]), "+f"(d[3])
        : "r"(a[0]), "r"(a[1]), "r"(a[2]), "r"(a[3]), "r"(bfr[0]), "r"(bfr[1]));
}
__device__ __forceinline__ void ldsm_x4(uint32_t* r, uint32_t saddr) {
    asm volatile("ldmatrix.sync.aligned.m8n8.x4.shared.b16 {%0,%1,%2,%3}, [%4];"
                 : "=r"(r[0]), "=r"(r[1]), "=r"(r[2]), "=r"(r[3]) : "r"(saddr));
}
__device__ __forceinline__ void ldsm_x4_t(uint32_t* r, uint32_t saddr) {
    asm volatile("ldmatrix.sync.aligned.m8n8.x4.trans.shared.b16 {%0,%1,%2,%3}, [%4];"
                 : "=r"(r[0]), "=r"(r[1]), "=r"(r[2]), "=r"(r[3]) : "r"(saddr));
}
__device__ __forceinline__ uint32_t pack_h2(float lo, float hi) {
    uint32_t u;
    asm("cvt.rn.f16x2.f32 %0, %1, %2;" : "=r"(u) : "f"(hi), "f"(lo));  // lo -> .x
    return u;
}

// ===========================================================================
// K1: projections + x->half conversion (x is already being read here).
// ===========================================================================
__global__ void __launch_bounds__(256)
k1_proj(const float* __restrict__ x, const float* __restrict__ W1,
        const float* __restrict__ W2) {
    __shared__ float W1T[NR][ND];
    __shared__ float W2s[NR][ND];
    int tid = threadIdx.x;
    for (int idx = tid; idx < ND * NR; idx += 256) {
        int d = idx / NR, r = idx % NR;
        W1T[r][d] = W1[idx];               // W1 [D, R], r fastest
    }
    for (int idx = tid; idx < NR * ND; idx += 256) {
        W2s[idx / ND][idx % ND] = W2[idx]; // W2 [R, D], d fastest
    }
    __syncthreads();

    int warp = tid >> 5, lane = tid & 31;
    int row0 = blockIdx.x * 32 + warp * 4;
    const float* xr0 = x + (size_t)row0 * ND;
    __half* xh0 = g_xh + (size_t)row0 * ND;

    float accL[4][NR], accR[4][NR];
#pragma unroll
    for (int i = 0; i < 4; i++)
#pragma unroll
        for (int r = 0; r < NR; r++) { accL[i][r] = 0.f; accR[i][r] = 0.f; }

#pragma unroll
    for (int k = 0; k < ND / 32; k++) {
        int d = lane + 32 * k;
        float xv[4];
#pragma unroll
        for (int i = 0; i < 4; i++) {
            xv[i] = xr0[(size_t)i * ND + d];
            xh0[(size_t)i * ND + d] = __float2half_rn(xv[i]);
        }
#pragma unroll
        for (int r = 0; r < NR; r++) {
            float w1 = W1T[r][d];
            float w2 = W2s[r][d];
#pragma unroll
            for (int i = 0; i < 4; i++) {
                accL[i][r] += xv[i] * w1;
                accR[i][r] += xv[i] * w2;
            }
        }
    }
#pragma unroll
    for (int i = 0; i < 4; i++)
#pragma unroll
        for (int r = 0; r < NR; r++) {
#pragma unroll
            for (int off = 16; off; off >>= 1) {
                accL[i][r] += __shfl_down_sync(0xffffffffu, accL[i][r], off);
                accR[i][r] += __shfl_down_sync(0xffffffffu, accR[i][r], off);
            }
        }
    if (lane == 0) {
#pragma unroll
        for (int i = 0; i < 4; i++) {
            float* lp = g_left   + (size_t)(row0 + i) * NR;
            float* rp = g_rightT + (size_t)(row0 + i) * NR;
#pragma unroll
            for (int r = 0; r < NR; r++) {
                lp[r] = accL[i][r] * INV_SQRT_DK;
                rp[r] = accR[i][r];
            }
        }
    }
}

// ===========================================================================
// K3: fp16 warp-MMA (m16n8k16) attention-weighted sum.
//   CTA: M=128 queries x N=256 d-cols, 512 threads (16 warps = 2m x 8n,
//   warp tile 64x32). K-loop 2048 keys, KC=64 (4 k16 steps), 32 chunks.
//   As: exp-scores half [128 m][72] (64 k + 8 pad), ldmatrix.x4 A-frags.
//   Bh: x half [k][n] row-major [64][264] (256 + 8 pad), double-buffered,
//       cp.async direct from g_xh; ldmatrix.x4.trans B-frags.
//   Both strides give conflict-free 8-row ldmatrix phases.
//   Prefetch issued AFTER the chunk barrier (no cross-warp WAR on the buffer).
//   Unnormalized accumulation; per-row denominator in regs -> epilogue.
// ===========================================================================
#define KC 64
#define NCHUNK (NA / KC)          // 32
#define AS_STRIDE 72              // halves
#define BH_STRIDE 264             // halves
#define BH_CHUNK (KC * BH_STRIDE) // halves
// dynamic smem layout (bytes)
#define OFF_AS 0                  // 128*72*2      = 18432
#define OFF_BH 18432              // 2*64*264*2    = 67584
#define OFF_RT 86016              // 2*10*64*4     = 5120
#define OFF_SL 91136              // 128*4         = 512
#define SMEM_K3 91648

__global__ void __launch_bounds__(512, 1)
k3_attn_mma(float* __restrict__ out) {
    extern __shared__ char smem[];
    __half* As  = (__half*)(smem + OFF_AS);    // [128][72]
    float*  RtT = (float*)(smem + OFF_RT);     // [2][10][64]
    float*  sl  = (float*)(smem + OFF_SL);     // [128]
    uint32_t sb = smem_u32(smem);

    int tid = threadIdx.x;
    int wid = tid >> 5, lane = tid & 31;
    int b  = blockIdx.z;
    int a0 = blockIdx.x * 128;
    int n0 = blockIdx.y * 256;

    // score-gen mapping: 1 row x 16 k per thread
    int mg = tid >> 2, kg = tid & 3;
    float ls[NR];
    {
        const float* lp = g_left + ((size_t)b * NA + a0 + mg) * NR;
#pragma unroll
        for (int r = 0; r < NR; r++) ls[r] = lp[r];
    }
    float lacc = 0.f;

    // MMA mapping: 16 warps = 2(m) x 8(n)
    int wm = wid >> 3, wn = wid & 7;
    int fs = lane & 3, fq = lane >> 2;
    float acc[4][4][4];
#pragma unroll
    for (int mt = 0; mt < 4; mt++)
#pragma unroll
        for (int nt = 0; nt < 4; nt++)
#pragma unroll
            for (int q = 0; q < 4; q++) acc[mt][nt][q] = 0.f;

    const __half* xhb = g_xh + (size_t)b * NA * ND;

    // ---- prologue: prefetch Bh[0], RtT[0] ----
    // 2048 x 16B units: 64 rows x 32 units/row (8 halves per unit)
#pragma unroll
    for (int it = 0; it < 4; it++) {
        int u = tid + 512 * it;
        int kk = u >> 5, c8 = u & 31;
        uint32_t dst = sb + OFF_BH + (uint32_t)(kk * BH_STRIDE + 8 * c8) * 2;
        cp_async16(dst, xhb + (size_t)kk * ND + n0 + 8 * c8);
    }
    CP_COMMIT();
    for (int idx = tid; idx < KC * NR; idx += 512) {
        int k = idx / NR, r = idx % NR;
        RtT[r * KC + k] = g_rightT[((size_t)b * NA + k) * NR + r];
    }

    for (int c = 0; c < NCHUNK; c++) {
        int buf = c & 1;

        CP_WAIT0();        // Bh[c] landed (all outstanding groups)
        __syncthreads();   // visible to all; As & other Bh buffer free

        // prefetch Bh[c+1] into the other buffer (safe: all MMAs of c-1 done)
        if (c + 1 < NCHUNK) {
            int pb = (c + 1) & 1;
#pragma unroll
            for (int it = 0; it < 4; it++) {
                int u = tid + 512 * it;
                int kk = u >> 5, c8 = u & 31;
                uint32_t dst = sb + OFF_BH + (uint32_t)(pb * BH_CHUNK + kk * BH_STRIDE + 8 * c8) * 2;
                cp_async16(dst, xhb + (size_t)((c + 1) * KC + kk) * ND + n0 + 8 * c8);
            }
            CP_COMMIT();
        }

        // prefetch RtT for chunk c+1 (other RtT buffer; readers use c&1)
        if (c + 1 < NCHUNK) {
            float* rtw = RtT + ((c + 1) & 1) * (NR * KC);
            for (int idx = tid; idx < KC * NR; idx += 512) {
                int k = idx / NR, r = idx % NR;
                rtw[r * KC + k] = g_rightT[((size_t)b * NA + (c + 1) * KC + k) * NR + r];
            }
        }

        // ---- score-gen: P' = exp(score) -> half into As[mg][16kg..16kg+15] ----
        {
            const float* rt = RtT + (c & 1) * (NR * KC);
            float sc[16];
#pragma unroll
            for (int j = 0; j < 16; j++) sc[j] = 0.f;
#pragma unroll
            for (int r = 0; r < NR; r++) {
                float lv = ls[r];
                const float* rp = rt + r * KC + 16 * kg;
#pragma unroll
                for (int j4 = 0; j4 < 4; j4++) {
                    float4 rv = *(const float4*)(rp + 4 * j4);
                    sc[4 * j4 + 0] += lv * rv.x;
                    sc[4 * j4 + 1] += lv * rv.y;
                    sc[4 * j4 + 2] += lv * rv.z;
                    sc[4 * j4 + 3] += lv * rv.w;
                }
            }
            float e[16];
            float s = 0.f;
#pragma unroll
            for (int j = 0; j < 16; j++) { e[j] = __expf(sc[j]); s += e[j]; }
            lacc += s;
            uint4 t0, t1;
            t0.x = pack_h2(e[0],  e[1]);  t0.y = pack_h2(e[2],  e[3]);
            t0.z = pack_h2(e[4],  e[5]);  t0.w = pack_h2(e[6],  e[7]);
            t1.x = pack_h2(e[8],  e[9]);  t1.y = pack_h2(e[10], e[11]);
            t1.z = pack_h2(e[12], e[13]); t1.w = pack_h2(e[14], e[15]);
            uint32_t* aw = (uint32_t*)(As + mg * AS_STRIDE + 16 * kg);
            *(uint4*)(aw)     = t0;
            *(uint4*)(aw + 4) = t1;
        }
        __syncthreads();   // As staged

        // ---- MMAs: 4 k16 steps; ldmatrix fragments ----
        uint32_t bbase = sb + OFF_BH + (uint32_t)buf * BH_CHUNK * 2;
#pragma unroll
        for (int ks = 0; ks < 4; ks++) {
            uint32_t afr[4][4], bfr[4][2];
            // A: 4 tiles 16x16 at rows wm*64+mt*16, cols ks*16
            {
                int arow = wm * 64 + (lane & 15);
                int acol = ks * 16 + (lane >> 4) * 8;
                uint32_t base = sb + OFF_AS + (uint32_t)(arow * AS_STRIDE + acol) * 2;
#pragma unroll
                for (int mt = 0; mt < 4; mt++)
                    ldsm_x4(afr[mt], base + (uint32_t)(mt * 16 * AS_STRIDE) * 2);
            }
            // B: 2 trans tiles cover 4 n8-frags at k=ks*16
            {
                int brow = ks * 16 + (lane & 15);
                int bcol = wn * 32 + (lane >> 4) * 8;
                uint32_t base = bbase + (uint32_t)(brow * BH_STRIDE + bcol) * 2;
#pragma unroll
                for (int np = 0; np < 2; np++) {
                    uint32_t q[4];
                    ldsm_x4_t(q, base + (uint32_t)(np * 16) * 2);
                    bfr[2 * np][0]     = q[0]; bfr[2 * np][1]     = q[1];
                    bfr[2 * np + 1][0] = q[2]; bfr[2 * np + 1][1] = q[3];
                }
            }
#pragma unroll
            for (int mt = 0; mt < 4; mt++)
#pragma unroll
                for (int nt = 0; nt < 4; nt++)
                    mma_f16(acc[mt][nt], afr[mt], bfr[nt]);
        }
    }

    // ---- softmax denominators: reduce over the 4 kg threads ----
    lacc += __shfl_xor_sync(0xffffffffu, lacc, 1);
    lacc += __shfl_xor_sync(0xffffffffu, lacc, 2);
    if (kg == 0) sl[mg] = lacc;
    __syncthreads();

    // ---- epilogue: normalize + store ----
#pragma unroll
    for (int mt = 0; mt < 4; mt++) {
        int r0 = wm * 64 + mt * 16 + fq;
        int r1 = r0 + 8;
        float inv0 = 1.0f / sl[r0];
        float inv1 = 1.0f / sl[r1];
        float* op0 = out + ((size_t)b * NA + a0 + r0) * ND + n0;
        float* op1 = out + ((size_t)b * NA + a0 + r1) * ND + n0;
#pragma unroll
        for (int nt = 0; nt < 4; nt++) {
            int col = wn * 32 + nt * 8 + 2 * fs;
            float2 v0 = make_float2(acc[mt][nt][0] * inv0, acc[mt][nt][1] * inv0);
            float2 v1 = make_float2(acc[mt][nt][2] * inv1, acc[mt][nt][3] * inv1);
            *(float2*)&op0[col] = v0;
            *(float2*)&op1[col] = v1;
        }
    }
}

// ---------------------------------------------------------------------------
extern "C" void kernel_launch(void* const* d_in, const int* in_sizes, int n_in,
                              void* d_out, int out_size) {
    const float* x  = (const float*)d_in[0];
    const float* W1 = (const float*)d_in[1];
    const float* W2 = (const float*)d_in[2];
    float* out = (float*)d_out;

    static bool attr_set = false;
    if (!attr_set) {
        cudaFuncSetAttribute(k3_attn_mma, cudaFuncAttributeMaxDynamicSharedMemorySize, SMEM_K3);
        attr_set = true;
    }

    k1_proj<<<(NB * NA) / 32, 256>>>(x, W1, W2);
    k3_attn_mma<<<dim3(NA / 128, ND / 256, NB), 512, SMEM_K3>>>(out);
}